// round 1
// baseline (speedup 1.0000x reference)
#include <cuda_runtime.h>

// EntmaxBisect: alpha=1.5, 50-iter bisection over last dim (4096), rows = 8*2048 = 16384.
//
// Mathematical reduction (see analysis): with p = 1/4095, every positive term
// (Xs_i - t)^p lies in (0.975, 1), so sum(Z) >= 1  <=>  count(Xs > t) >= 2
// <=>  second_largest(Xs) > t.  The bisection therefore only depends on the
// row's top-2 values, and is replicated bit-exactly on the reference's fp32
// lattice with a scalar loop.

#define D        4096
#define THREADS  256
#define PER_THR  16          // D / THREADS
#define N_ITER   50

__global__ __launch_bounds__(THREADS, 1)
void entmax_bisect_kernel(const float* __restrict__ X, float* __restrict__ out)
{
    const unsigned long long row = blockIdx.x;
    const float* __restrict__ xrow = X + row * (unsigned long long)D;
    float* __restrict__ orow = out + row * (unsigned long long)D;

    const int tid  = threadIdx.x;
    const int lane = tid & 31;
    const int wid  = tid >> 5;

    // ---- load 16 floats/thread (4x float4, coalesced), Xs = 0.5*X (exact) ----
    float xs[PER_THR];
    const float4* __restrict__ x4 = reinterpret_cast<const float4*>(xrow);
    #pragma unroll
    for (int j = 0; j < 4; j++) {
        float4 v = x4[tid + j * THREADS];
        xs[4*j + 0] = 0.5f * v.x;
        xs[4*j + 1] = 0.5f * v.y;
        xs[4*j + 2] = 0.5f * v.z;
        xs[4*j + 3] = 0.5f * v.w;
    }

    // ---- per-thread top-2 (order statistics with multiplicity) ----
    float m1 = -__int_as_float(0x7f800000);   // -inf
    float m2 = m1;
    #pragma unroll
    for (int k = 0; k < PER_THR; k++) {
        float v = xs[k];
        if (v > m1) { m2 = m1; m1 = v; }
        else if (v > m2) { m2 = v; }
    }

    // ---- warp top-2 reduce ----
    #pragma unroll
    for (int off = 16; off > 0; off >>= 1) {
        float b1 = __shfl_down_sync(0xffffffffu, m1, off);
        float b2 = __shfl_down_sync(0xffffffffu, m2, off);
        float n1 = fmaxf(m1, b1);
        float n2 = fmaxf(fminf(m1, b1), fmaxf(m2, b2));
        m1 = n1; m2 = n2;
    }

    __shared__ float sm1[8];
    __shared__ float sm2[8];
    __shared__ float ssum[8];
    __shared__ float sbc[2];     // [0] = final t, [1] = total sum

    if (lane == 0) { sm1[wid] = m1; sm2[wid] = m2; }
    __syncthreads();

    if (tid == 0) {
        float M = sm1[0], S = sm2[0];
        #pragma unroll
        for (int w = 1; w < 8; w++) {
            float b1 = sm1[w], b2 = sm2[w];
            float n1 = fmaxf(M, b1);
            S = fmaxf(fminf(M, b1), fmaxf(S, b2));
            M = n1;
        }
        // ---- scalar fp32 bisection, bit-faithful to the reference lattice ----
        float tmin = M - 1.0f;
        float tmax = M - 0.015625f;          // M - 4096^(1-1.5), exact constant
        float diff = tmax - tmin;
        float t = tmin;
        #pragma unroll 1
        for (int i = 0; i < N_ITER; i++) {
            diff = diff * 0.5f;
            t = tmin + diff;
            if (S > t) tmin = t;             // == (sum(Z)-1 >= 0), see analysis
        }
        sbc[0] = t;                          // final candidate t (as in reference)
    }
    __syncthreads();

    const float t = sbc[0];
    const float p = 1.0f / 4095.0f;          // == fp32(1/(d-1))

    // ---- local partial sum of Z (powf only fires on ~2 active lanes/row) ----
    float lsum = 0.0f;
    #pragma unroll
    for (int k = 0; k < PER_THR; k++) {
        float u = xs[k] - t;
        if (u > 0.0f) lsum += powf(u, p);
    }
    #pragma unroll
    for (int off = 16; off > 0; off >>= 1)
        lsum += __shfl_down_sync(0xffffffffu, lsum, off);
    if (lane == 0) ssum[wid] = lsum;
    __syncthreads();
    if (tid == 0) {
        float tot = 0.0f;
        #pragma unroll
        for (int w = 0; w < 8; w++) tot += ssum[w];
        sbc[1] = tot;
    }
    __syncthreads();

    const float inv = 1.0f / sbc[1];

    // ---- write normalized Z, coalesced float4 stores ----
    float4* __restrict__ o4 = reinterpret_cast<float4*>(orow);
    #pragma unroll
    for (int j = 0; j < 4; j++) {
        float4 r;
        float u;
        u = xs[4*j + 0] - t; r.x = (u > 0.0f) ? powf(u, p) * inv : 0.0f;
        u = xs[4*j + 1] - t; r.y = (u > 0.0f) ? powf(u, p) * inv : 0.0f;
        u = xs[4*j + 2] - t; r.z = (u > 0.0f) ? powf(u, p) * inv : 0.0f;
        u = xs[4*j + 3] - t; r.w = (u > 0.0f) ? powf(u, p) * inv : 0.0f;
        o4[tid + j * THREADS] = r;
    }
}

extern "C" void kernel_launch(void* const* d_in, const int* in_sizes, int n_in,
                              void* d_out, int out_size)
{
    const float* X = (const float*)d_in[0];
    float* out = (float*)d_out;
    const int n = in_sizes[0];          // 8*2048*4096
    const int rows = n / D;             // 16384
    entmax_bisect_kernel<<<rows, THREADS>>>(X, out);
}

// round 2
// speedup vs baseline: 1.1358x; 1.1358x over previous
#include <cuda_runtime.h>

// EntmaxBisect: alpha=1.5, 50-iter bisection over last dim (4096), rows = 8*2048 = 16384.
//
// Reduction: with p = 1/4095, every positive term (Xs_i - t)^p lies in
// (0.975, 1], so sum(Z) >= 1  <=>  count(Xs > t) >= 2  <=>  second_largest(Xs) > t.
// The bisection depends only on the row's top-2, replicated bit-exactly on the
// reference's fp32 lattice with a scalar loop (returns the final TESTED t,
// exactly as the reference does).

#define D        4096
#define THREADS  512
#define PER_THR  8           // D / THREADS
#define NWARPS   16
#define N_ITER   50

__global__ __launch_bounds__(THREADS, 4)
void entmax_bisect_kernel(const float* __restrict__ X, float* __restrict__ out)
{
    const unsigned long long row = blockIdx.x;
    const float* __restrict__ xrow = X + row * (unsigned long long)D;
    float* __restrict__ orow = out + row * (unsigned long long)D;

    const int tid  = threadIdx.x;
    const int lane = tid & 31;
    const int wid  = tid >> 5;

    // ---- load 8 floats/thread (2x float4, coalesced), Xs = 0.5*X (exact) ----
    float xs[PER_THR];
    const float4* __restrict__ x4 = reinterpret_cast<const float4*>(xrow);
    float4 v0 = x4[tid];
    float4 v1 = x4[tid + THREADS];
    xs[0] = 0.5f * v0.x;  xs[1] = 0.5f * v0.y;
    xs[2] = 0.5f * v0.z;  xs[3] = 0.5f * v0.w;
    xs[4] = 0.5f * v1.x;  xs[5] = 0.5f * v1.y;
    xs[6] = 0.5f * v1.z;  xs[7] = 0.5f * v1.w;

    // ---- per-thread top-2, branchless (3 min/max per element) ----
    float m1 = -__int_as_float(0x7f800000);   // -inf
    float m2 = m1;
    #pragma unroll
    for (int k = 0; k < PER_THR; k++) {
        float v  = xs[k];
        float lo = fminf(m1, v);
        m1 = fmaxf(m1, v);
        m2 = fmaxf(m2, lo);
    }

    // ---- warp top-2 reduce ----
    #pragma unroll
    for (int off = 16; off > 0; off >>= 1) {
        float b1 = __shfl_down_sync(0xffffffffu, m1, off);
        float b2 = __shfl_down_sync(0xffffffffu, m2, off);
        float lo = fminf(m1, b1);
        m1 = fmaxf(m1, b1);
        m2 = fmaxf(fmaxf(m2, b2), lo);
    }

    __shared__ float sm1[NWARPS];
    __shared__ float sm2[NWARPS];
    __shared__ float ssum[NWARPS];
    __shared__ float sbc;        // final t

    if (lane == 0) { sm1[wid] = m1; sm2[wid] = m2; }
    __syncthreads();

    if (tid == 0) {
        float M = sm1[0], S = sm2[0];
        #pragma unroll
        for (int w = 1; w < NWARPS; w++) {
            float b1 = sm1[w];
            float lo = fminf(M, b1);
            M = fmaxf(M, b1);
            S = fmaxf(fmaxf(S, sm2[w]), lo);
        }
        // ---- scalar fp32 bisection, bit-faithful to the reference lattice ----
        float tmin = M - 1.0f;
        float tmax = M - 0.015625f;          // M - 4096^(1-1.5), exact constant
        float diff = tmax - tmin;
        float t = tmin;
        #pragma unroll 1
        for (int i = 0; i < N_ITER; i++) {
            diff = diff * 0.5f;
            t = tmin + diff;
            if (S > t) tmin = t;             // == (sum(Z)-1 >= 0)
        }
        sbc = t;                             // final TESTED t, as in reference
    }
    __syncthreads();

    const float t = sbc;
    const float p = 1.0f / 4095.0f;          // == fp32(1/(d-1))

    // ---- partial sum of Z (powf fires only on the 1-2 active lanes/row) ----
    float lsum = 0.0f;
    #pragma unroll
    for (int k = 0; k < PER_THR; k++) {
        float u = xs[k] - t;
        if (u > 0.0f) lsum += powf(u, p);
    }
    #pragma unroll
    for (int off = 16; off > 0; off >>= 1)
        lsum += __shfl_down_sync(0xffffffffu, lsum, off);
    if (lane == 0) ssum[wid] = lsum;
    __syncthreads();

    // all threads redundantly sum 16 warp partials (15 FADD, no extra barrier)
    float tot = 0.0f;
    #pragma unroll
    for (int w = 0; w < NWARPS; w++) tot += ssum[w];
    const float inv = 1.0f / tot;

    // ---- write normalized Z, coalesced float4 stores ----
    float4* __restrict__ o4 = reinterpret_cast<float4*>(orow);
    float4 r0, r1;
    float u;
    u = xs[0] - t; r0.x = (u > 0.0f) ? powf(u, p) * inv : 0.0f;
    u = xs[1] - t; r0.y = (u > 0.0f) ? powf(u, p) * inv : 0.0f;
    u = xs[2] - t; r0.z = (u > 0.0f) ? powf(u, p) * inv : 0.0f;
    u = xs[3] - t; r0.w = (u > 0.0f) ? powf(u, p) * inv : 0.0f;
    u = xs[4] - t; r1.x = (u > 0.0f) ? powf(u, p) * inv : 0.0f;
    u = xs[5] - t; r1.y = (u > 0.0f) ? powf(u, p) * inv : 0.0f;
    u = xs[6] - t; r1.z = (u > 0.0f) ? powf(u, p) * inv : 0.0f;
    u = xs[7] - t; r1.w = (u > 0.0f) ? powf(u, p) * inv : 0.0f;
    o4[tid] = r0;
    o4[tid + THREADS] = r1;
}

extern "C" void kernel_launch(void* const* d_in, const int* in_sizes, int n_in,
                              void* d_out, int out_size)
{
    const float* X = (const float*)d_in[0];
    float* out = (float*)d_out;
    const int n = in_sizes[0];          // 8*2048*4096
    const int rows = n / D;             // 16384
    entmax_bisect_kernel<<<rows, THREADS>>>(X, out);
}